// round 11
// baseline (speedup 1.0000x reference)
#include <cuda_runtime.h>
#include <cuda_fp16.h>
#include <cstdint>
#include <stdint.h>
#include <math.h>

// Problem constants
#define Bdim 2
#define Sdim 2048
#define Hdim 2048
#define NHdim 16
#define Ddim 128
#define FFdim 8192
#define Mrows (Bdim*Sdim)   // 4096

// -------- scratch (device globals; no allocation) --------
__device__ float g_hidden[(size_t)Mrows*Hdim];   // residual+attn_out
__device__ float g_cos[Sdim*64];
__device__ float g_sin[Sdim*64];
__device__ __half g_qkvh[(size_t)Mrows*3*Hdim];  // QKV gemm out (half)
__device__ __half g_qh[(size_t)Mrows*Hdim];      // [B,NH,S,D]
__device__ __half g_kh[(size_t)Mrows*Hdim];
__device__ __half g_vh[(size_t)Mrows*Hdim];
__device__ __half g_vt[(size_t)Mrows*Hdim];      // [B,NH,D,S]
__device__ __half g_xh[(size_t)Mrows*Hdim];
__device__ __half g_ctxh[(size_t)Mrows*Hdim];
__device__ __half g_interh[(size_t)Mrows*FFdim];
__device__ __half g_wqkvh[(size_t)3*Hdim*Hdim];
__device__ __half g_wdh[(size_t)Hdim*Hdim];
__device__ __half g_w1h[(size_t)FFdim*Hdim];
__device__ __half g_w2h[(size_t)Hdim*FFdim];

// ============================ helpers ============================
__device__ __forceinline__ uint32_t smem_u32(const void* p) {
    uint32_t a;
    asm("{ .reg .u64 t; cvta.to.shared.u64 t, %1; cvt.u32.u64 %0, t; }" : "=r"(a) : "l"(p));
    return a;
}
__device__ __forceinline__ void ldsm4(uint32_t* r, uint32_t addr) {
    asm volatile("ldmatrix.sync.aligned.m8n8.x4.shared.b16 {%0,%1,%2,%3}, [%4];"
        : "=r"(r[0]), "=r"(r[1]), "=r"(r[2]), "=r"(r[3]) : "r"(addr));
}
__device__ __forceinline__ void mma16816(float* c, const uint32_t* a, uint32_t b0, uint32_t b1) {
    asm("mma.sync.aligned.m16n8k16.row.col.f32.f16.f16.f32 "
        "{%0,%1,%2,%3}, {%4,%5,%6,%7}, {%8,%9}, {%0,%1,%2,%3};"
        : "+f"(c[0]), "+f"(c[1]), "+f"(c[2]), "+f"(c[3])
        : "r"(a[0]), "r"(a[1]), "r"(a[2]), "r"(a[3]), "r"(b0), "r"(b1));
}
// fp16-accumulator variant (2 packed-b32 C regs)
__device__ __forceinline__ void mma16816h(uint32_t* c, const uint32_t* a, uint32_t b0, uint32_t b1) {
    asm("mma.sync.aligned.m16n8k16.row.col.f16.f16.f16.f16 "
        "{%0,%1}, {%2,%3,%4,%5}, {%6,%7}, {%0,%1};"
        : "+r"(c[0]), "+r"(c[1])
        : "r"(a[0]), "r"(a[1]), "r"(a[2]), "r"(a[3]), "r"(b0), "r"(b1));
}
__device__ __forceinline__ void cp16(uint32_t dst, const void* src) {
    asm volatile("cp.async.cg.shared.global [%0], [%1], 16;"
        :: "r"(dst), "l"(__cvta_generic_to_global(src)) : "memory");
}
#define CP_COMMIT() asm volatile("cp.async.commit_group;" ::: "memory")
#define CP_WAIT(n)  asm volatile("cp.async.wait_group %0;" :: "n"(n) : "memory")

__device__ __forceinline__ float ex2(float x) {
    float r;
    asm("ex2.approx.ftz.f32 %0, %1;" : "=f"(r) : "f"(x));
    return r;
}
__device__ __forceinline__ uint32_t f22u(float a, float b) {
    __half2 h = __floats2half2_rn(a, b);
    return *(uint32_t*)&h;
}

// swizzled smem offset: rows of 64B (32 halfs), 16B chunk XOR (row>>1)&3
__device__ __forceinline__ uint32_t swoff(int row, int chunk) {
    return (uint32_t)(row * 64 + ((chunk ^ ((row >> 1) & 3)) << 4));
}

// ============================ weight convert kernel (float4 vectorized) ============================
__global__ void cvt_kernel(const float* __restrict__ in, __half* __restrict__ hi, int n8) {
    int i = blockIdx.x * blockDim.x + threadIdx.x;
    if (i >= n8) return;
    float4 a = ((const float4*)in)[(size_t)i * 2];
    float4 b = ((const float4*)in)[(size_t)i * 2 + 1];
    __half2 h0 = __floats2half2_rn(a.x, a.y), h1 = __floats2half2_rn(a.z, a.w);
    __half2 h2 = __floats2half2_rn(b.x, b.y), h3 = __floats2half2_rn(b.z, b.w);
    ((uint4*)hi)[i] = make_uint4(*(uint32_t*)&h0, *(uint32_t*)&h1,
                                 *(uint32_t*)&h2, *(uint32_t*)&h3);
}

// ============================ HMMA GEMM (fp32 acc, 256x128 tile) — QKV ============================
// EPI: 3 = bias -> Ch half
#define GBM 256
#define GBN 128
#define NSTAGE 3
#define STAGE1 24576     // Ah 16K | Wh 8K
#define HM_SMEM (NSTAGE*STAGE1)

template<int EPI>
__global__ void __launch_bounds__(512, 1) hgemm(
    const __half* __restrict__ Ah_, const __half* __restrict__ Wh_,
    const float* __restrict__ bias, const float* __restrict__ res,
    float* __restrict__ C, __half* __restrict__ Ch,
    int M, int N, int K)
{
    extern __shared__ char sm[];
    uint32_t smb = smem_u32(sm);
    int tid = threadIdx.x;
    int lane = tid & 31, wid = tid >> 5;
    int wm = (wid & 3) * 64;
    int wn = (wid >> 2) * 32;
    int bm = blockIdx.y * GBM, bn = blockIdx.x * GBN;

    int aidx = tid * 2;
    int arow = aidx >> 2, ach = aidx & 3;
    int wrow = tid >> 2, wch = tid & 3;
    const __half* pAh = Ah_ + (size_t)(bm + arow) * K + ach * 8;
    const __half* pWh = Wh_ + (size_t)(bn + wrow) * K + wch * 8;
    uint32_t dA0 = swoff(arow, ach), dA1 = swoff(arow, ach + 1);
    uint32_t dW  = swoff(wrow, wch);

    float acc[4][4][4];
#pragma unroll
    for (int i = 0; i < 4; i++)
#pragma unroll
        for (int j = 0; j < 4; j++)
#pragma unroll
            for (int q = 0; q < 4; q++) acc[i][j][q] = 0.f;

    int mat = lane >> 3, mr = lane & 7;
    int fr_row = (mat & 1) * 8 + mr;
    int fr_ch  = mat >> 1;

    const int NC = K >> 5;

    auto load_stage = [&](int c) {
        uint32_t base = smb + (uint32_t)(c % NSTAGE) * STAGE1;
        size_t ko = (size_t)c * 32;
        cp16(base + 0     + dA0, pAh + ko);
        cp16(base + 0     + dA1, pAh + ko + 8);
        cp16(base + 16384 + dW,  pWh + ko);
    };

#pragma unroll
    for (int c = 0; c < NSTAGE - 1; c++) { load_stage(c); CP_COMMIT(); }

    for (int c = 0; c < NC; c++) {
        CP_WAIT(NSTAGE - 2);
        __syncthreads();
        if (c + NSTAGE - 1 < NC) { load_stage(c + NSTAGE - 1); }
        CP_COMMIT();

        uint32_t base = smb + (uint32_t)(c % NSTAGE) * STAGE1;
#pragma unroll
        for (int kk = 0; kk < 2; kk++) {
            uint32_t ah[4][4], bh[2][4];
#pragma unroll
            for (int i = 0; i < 4; i++) {
                uint32_t off = swoff(wm + i * 16 + fr_row, kk * 2 + fr_ch);
                ldsm4(ah[i], base + 0 + off);
            }
#pragma unroll
            for (int g = 0; g < 2; g++) {
                uint32_t off = swoff(wn + g * 16 + fr_row, kk * 2 + fr_ch);
                ldsm4(bh[g], base + 16384 + off);
            }
#pragma unroll
            for (int i = 0; i < 4; i++) {
#pragma unroll
                for (int jj = 0; jj < 4; jj++) {
                    int g = jj >> 1, h = jj & 1;
                    mma16816(acc[i][jj], ah[i], bh[g][h], bh[g][h+2]);
                }
            }
        }
    }

    int tr = lane >> 2;
    int tc = (lane & 3) * 2;
#pragma unroll
    for (int i = 0; i < 4; i++) {
#pragma unroll
        for (int jj = 0; jj < 4; jj++) {
            int n0 = bn + wn + jj * 8 + tc;
            float b0 = bias[n0], b1 = bias[n0 + 1];
#pragma unroll
            for (int half = 0; half < 2; half++) {
                int m = bm + wm + i * 16 + tr + half * 8;
                size_t idx = (size_t)m * N + n0;
                float v0 = acc[i][jj][half * 2 + 0] + b0;
                float v1 = acc[i][jj][half * 2 + 1] + b1;
                if (EPI == 3) {
                    *(__half2*)(Ch + idx) = __floats2half2_rn(v0, v1);
                } else {
                    if (EPI == 2) { v0 += res[idx]; v1 += res[idx + 1]; }
                    *(float2*)(C + idx) = make_float2(v0, v1);
                }
            }
        }
    }
}

// ============================ HMMA GEMM fp16-acc (128x128 tile, K64 spill) ============================
// EPI: 1 = bias+GELU -> Ch half ; 2 = bias+residual -> C fp32
#define H2STAGE 16384    // Ah 8K | Wh 8K
#define H2_SMEM (NSTAGE*H2STAGE)

template<int EPI>
__global__ void __launch_bounds__(512, 1) hgemm_h(
    const __half* __restrict__ Ah_, const __half* __restrict__ Wh_,
    const float* __restrict__ bias, const float* __restrict__ res,
    float* __restrict__ C, __half* __restrict__ Ch,
    int M, int N, int K)
{
    extern __shared__ char sm[];
    uint32_t smb = smem_u32(sm);
    int tid = threadIdx.x;
    int lane = tid & 31, wid = tid >> 5;
    int wm = (wid & 3) * 32;       // 4 warp-rows over 128
    int wn = (wid >> 2) * 32;      // 4 warp-cols over 128
    int bm = blockIdx.y * 128, bn = blockIdx.x * 128;

    // loaders: A/W each 128 rows x 4 chunks = 512 slots, 1 per thread
    int arow = tid >> 2, ach = tid & 3;
    const __half* pAh = Ah_ + (size_t)(bm + arow) * K + ach * 8;
    const __half* pWh = Wh_ + (size_t)(bn + arow) * K + ach * 8;
    uint32_t dA = swoff(arow, ach);

    float acc[2][4][4];
#pragma unroll
    for (int i = 0; i < 2; i++)
#pragma unroll
        for (int j = 0; j < 4; j++)
#pragma unroll
            for (int q = 0; q < 4; q++) acc[i][j][q] = 0.f;
    uint32_t hacc[2][4][2];

    int mat = lane >> 3, mr = lane & 7;
    int fr_row = (mat & 1) * 8 + mr;
    int fr_ch  = mat >> 1;

    const int NC = K >> 5;     // chunks of 32; spill every 2 (K=64 windows)

    auto load_stage = [&](int c) {
        uint32_t base = smb + (uint32_t)(c % NSTAGE) * H2STAGE;
        size_t ko = (size_t)c * 32;
        cp16(base + 0    + dA, pAh + ko);
        cp16(base + 8192 + dA, pWh + ko);
    };

#pragma unroll
    for (int c = 0; c < NSTAGE - 1; c++) { load_stage(c); CP_COMMIT(); }

    for (int c = 0; c < NC; c++) {
        CP_WAIT(NSTAGE - 2);
        __syncthreads();
        if (c + NSTAGE - 1 < NC) { load_stage(c + NSTAGE - 1); }
        CP_COMMIT();

        if ((c & 1) == 0) {
#pragma unroll
            for (int i = 0; i < 2; i++)
#pragma unroll
                for (int jj = 0; jj < 4; jj++) { hacc[i][jj][0] = 0u; hacc[i][jj][1] = 0u; }
        }

        uint32_t base = smb + (uint32_t)(c % NSTAGE) * H2STAGE;
#pragma unroll
        for (int kk = 0; kk < 2; kk++) {
            uint32_t ah[2][4], bh[2][4];
#pragma unroll
            for (int i = 0; i < 2; i++) {
                uint32_t off = swoff(wm + i * 16 + fr_row, kk * 2 + fr_ch);
                ldsm4(ah[i], base + 0 + off);
            }
#pragma unroll
            for (int g = 0; g < 2; g++) {
                uint32_t off = swoff(wn + g * 16 + fr_row, kk * 2 + fr_ch);
                ldsm4(bh[g], base + 8192 + off);
            }
#pragma unroll
            for (int i = 0; i < 2; i++) {
#pragma unroll
                for (int jj = 0; jj < 4; jj++) {
                    int g = jj >> 1, h = jj & 1;
                    mma16816h(hacc[i][jj], ah[i], bh[g][h], bh[g][h+2]);
                }
            }
        }

        if (c & 1) {  // spill fp16 window into fp32 accumulators
#pragma unroll
            for (int i = 0; i < 2; i++)
#pragma unroll
                for (int jj = 0; jj < 4; jj++) {
                    float2 lo = __half22float2(*(__half2*)&hacc[i][jj][0]);
                    float2 hi = __half22float2(*(__half2*)&hacc[i][jj][1]);
                    acc[i][jj][0] += lo.x; acc[i][jj][1] += lo.y;
                    acc[i][jj][2] += hi.x; acc[i][jj][3] += hi.y;
                }
        }
    }

    int tr = lane >> 2;
    int tc = (lane & 3) * 2;
#pragma unroll
    for (int i = 0; i < 2; i++) {
#pragma unroll
        for (int jj = 0; jj < 4; jj++) {
            int n0 = bn + wn + jj * 8 + tc;
            float b0 = bias[n0], b1 = bias[n0 + 1];
#pragma unroll
            for (int half = 0; half < 2; half++) {
                int m = bm + wm + i * 16 + tr + half * 8;
                size_t idx = (size_t)m * N + n0;
                float v0 = acc[i][jj][half * 2 + 0] + b0;
                float v1 = acc[i][jj][half * 2 + 1] + b1;
                if (EPI == 1) {
                    v0 = 0.5f * v0 * (1.0f + erff(v0 * 0.70710678118654752f));
                    v1 = 0.5f * v1 * (1.0f + erff(v1 * 0.70710678118654752f));
                    *(__half2*)(Ch + idx) = __floats2half2_rn(v0, v1);
                } else {
                    if (EPI == 2) { v0 += res[idx]; v1 += res[idx + 1]; }
                    *(float2*)(C + idx) = make_float2(v0, v1);
                }
            }
        }
    }
}

// ============================ LayerNorm -> fp16 ============================
__global__ void ln_kernel(const float* __restrict__ in, const float* __restrict__ w,
                          const float* __restrict__ b, __half* __restrict__ oh) {
    __shared__ float2 red[256];
    int row = blockIdx.x;
    const float* x = in + (size_t)row * Hdim;
    float s = 0.f, ss = 0.f;
    for (int i = threadIdx.x * 2; i < Hdim; i += 512) {
        float2 v = *(const float2*)(x + i);
        s += v.x + v.y;
        ss = fmaf(v.x, v.x, fmaf(v.y, v.y, ss));
    }
    red[threadIdx.x] = make_float2(s, ss);
    __syncthreads();
    for (int o = 128; o > 0; o >>= 1) {
        if (threadIdx.x < o) {
            float2 a = red[threadIdx.x], c = red[threadIdx.x + o];
            red[threadIdx.x] = make_float2(a.x + c.x, a.y + c.y);
        }
        __syncthreads();
    }
    float mean = red[0].x * (1.0f / Hdim);
    float var  = red[0].y * (1.0f / Hdim) - mean * mean;
    float rstd = rsqrtf(var + 1e-5f);
    for (int i = threadIdx.x * 2; i < Hdim; i += 512) {
        float2 v = *(const float2*)(x + i);
        float2 wv = *(const float2*)(w + i);
        float2 bv = *(const float2*)(b + i);
        float o0 = (v.x - mean) * rstd * wv.x + bv.x;
        float o1 = (v.y - mean) * rstd * wv.y + bv.y;
        *(__half2*)(oh + (size_t)row * Hdim + i) = __floats2half2_rn(o0, o1);
    }
}

// ============================ RoPE table (double precision trig) ============================
__global__ void rope_table_kernel() {
    int idx = blockIdx.x * blockDim.x + threadIdx.x;
    if (idx >= Sdim * 64) return;
    int s = idx >> 6, i = idx & 63;
    double invf = exp(-(double)i * (9.210340371976184 / 64.0)); // ln(10000)/64
    double th = (double)s * invf;
    g_cos[idx] = (float)cos(th);
    g_sin[idx] = (float)sin(th);
}

// ============================ QKV split + RoPE (half in, half out) ============================
__global__ void rope_kernel() {
    int row = blockIdx.x;      // b*S + s
    int h = blockIdx.y;
    int d = threadIdx.x;       // 0..127
    int s = row & (Sdim - 1);
    int b = row >> 11;
    const __half* src = g_qkvh + (size_t)row * (3 * Hdim) + h * (3 * Ddim);
    float q = __half2float(src[d]);
    float k = __half2float(src[Ddim + d]);
    __half v = src[2 * Ddim + d];
    int di = d & 63;
    float cs = g_cos[s * 64 + di];
    float sn = g_sin[s * 64 + di];
    float qp, kp;
    if (d < 64) { qp = -__half2float(src[d + 64]);      kp = -__half2float(src[Ddim + d + 64]); }
    else        { qp =  __half2float(src[d - 64]);      kp =  __half2float(src[Ddim + d - 64]); }
    size_t oidx = ((size_t)(b * NHdim + h) * Sdim + s) * Ddim + d;
    g_qh[oidx] = __float2half(q * cs + qp * sn);
    g_kh[oidx] = __float2half(k * cs + kp * sn);
    g_vh[oidx] = v;
}

// ============================ V transpose: [bh,S,D] -> [bh,D,S] ============================
__global__ void vt_kernel() {
    __shared__ __half tile[64][66];
    int bh = blockIdx.z;
    int s0 = blockIdx.x * 64, d0 = blockIdx.y * 64;
    const __half* src = g_vh + ((size_t)bh * Sdim + s0) * Ddim + d0;
#pragma unroll
    for (int i = 0; i < 16; i++) {
        int idx = threadIdx.x + i * 256;
        int r = idx >> 6, c = idx & 63;
        tile[r][c] = src[(size_t)r * Ddim + c];
    }
    __syncthreads();
    __half* dst = g_vt + ((size_t)bh * Ddim + d0) * Sdim + s0;
#pragma unroll
    for (int i = 0; i < 16; i++) {
        int idx = threadIdx.x + i * 256;
        int dr = idx >> 6, sc = idx & 63;
        dst[(size_t)dr * Sdim + sc] = tile[sc][dr];
    }
}

// ============================ HMMA flash attention (causal) ============================
#define AT_SMEM (32768 + 2*16384)

__global__ void __launch_bounds__(256, 1) attn_kernel() {
    extern __shared__ char sm[];
    uint32_t smb = smem_u32(sm);
    uint32_t qbase = smb;
    int tid = threadIdx.x;
    int lane = tid & 31, wid = tid >> 5;
    int qt = gridDim.x - 1 - blockIdx.x;
    int bh = blockIdx.y;

    const __half* Qg  = g_qh + ((size_t)bh * Sdim + (size_t)qt * 128) * Ddim;
    const __half* Kg  = g_kh + (size_t)bh * Sdim * Ddim;
    const __half* VTg = g_vt + (size_t)bh * Ddim * Sdim;

    {
        int row = tid >> 1, kb0 = (tid & 1) * 2;
#pragma unroll
        for (int i = 0; i < 8; i++) {
            int kb = kb0 + (i >> 2), ch = i & 3;
            cp16(qbase + kb * 8192 + swoff(row, ch), Qg + (size_t)row * 128 + kb * 32 + ch * 8);
        }
    }
    auto load_stage = [&](int kt) {
        uint32_t st = smb + 32768 + (uint32_t)(kt & 1) * 16384;
        const __half* kp = Kg + (size_t)kt * 32 * 128;
#pragma unroll
        for (int i = 0; i < 2; i++) {
            int idx = tid + i * 256;
            int krow = idx >> 4, kb = (idx >> 2) & 3, ch = idx & 3;
            cp16(st + kb * 2048 + swoff(krow, ch), kp + (size_t)krow * 128 + kb * 32 + ch * 8);
        }
        const __half* vp = VTg + (size_t)kt * 32;
#pragma unroll
        for (int i = 0; i < 2; i++) {
            int idx = tid + i * 256;
            int drow = idx >> 2, ch = idx & 3;
            cp16(st + 8192 + swoff(drow, ch), vp + (size_t)drow * Sdim + ch * 8);
        }
    };

    int nkt = 4 * qt + 4;
    load_stage(0); CP_COMMIT();
    load_stage(1); CP_COMMIT();
    CP_WAIT(1);
    __syncthreads();

    int mat = lane >> 3, mr = lane & 7;
    int fr_row = (mat & 1) * 8 + mr, fr_ch = mat >> 1;
    int wm = wid * 16;
    int tr = lane >> 2, tq = lane & 3;

    uint32_t qf[8][4];
#pragma unroll
    for (int kk = 0; kk < 8; kk++)
        ldsm4(qf[kk], qbase + (kk >> 1) * 8192 + swoff(wm + fr_row, (kk & 1) * 2 + fr_ch));

    float o_acc[16][4];
#pragma unroll
    for (int j = 0; j < 16; j++)
#pragma unroll
        for (int q = 0; q < 4; q++) o_acc[j][q] = 0.f;
    float m_run[2] = { -INFINITY, -INFINITY };
    float l_run[2] = { 0.f, 0.f };

    const float SC = 0.08838834764831845f * 1.4426950408889634f;
    int rowg0 = qt * 128 + wm + tr;

    for (int kt = 0; kt < nkt; kt++) {
        if (kt > 0) { CP_WAIT(1); __syncthreads(); }
        uint32_t st = smb + 32768 + (uint32_t)(kt & 1) * 16384;

        float s_acc[4][4];
#pragma unroll
        for (int j = 0; j < 4; j++)
#pragma unroll
            for (int q = 0; q < 4; q++) s_acc[j][q] = 0.f;
#pragma unroll
        for (int kk = 0; kk < 8; kk++) {
            uint32_t kf[2][4];
#pragma unroll
            for (int g = 0; g < 2; g++)
                ldsm4(kf[g], st + (kk >> 1) * 2048 + swoff(16 * g + fr_row, (kk & 1) * 2 + fr_ch));
#pragma unroll
            for (int g = 0; g < 2; g++)
#pragma unroll
                for (int h = 0; h < 2; h++)
                    mma16816(s_acc[2 * g + h], qf[kk], kf[g][h], kf[g][h + 2]);
        }

        float v[4][4];
#pragma unroll
        for (int j = 0; j < 4; j++)
#pragma unroll
            for (int q = 0; q < 4; q++) {
                int colg = kt * 32 + j * 8 + tq * 2 + (q & 1);
                int rowg = rowg0 + (q >> 1) * 8;
                float x = s_acc[j][q] * SC;
                v[j][q] = (colg <= rowg) ? x : -1e30f;
            }
        float mrow0 = -1e30f, mrow1 = -1e30f;
#pragma unroll
        for (int j = 0; j < 4; j++) {
            mrow0 = fmaxf(mrow0, fmaxf(v[j][0], v[j][1]));
            mrow1 = fmaxf(mrow1, fmaxf(v[j][2], v[j][3]));
        }
        mrow0 = fmaxf(mrow0, __shfl_xor_sync(0xFFFFFFFF, mrow0, 1));
        mrow0 = fmaxf(mrow0, __shfl_xor_sync(0xFFFFFFFF, mrow0, 2));
        mrow1 = fmaxf(mrow1, __shfl_xor_sync(0xFFFFFFFF, mrow1, 1));
        mrow1 = fmaxf(mrow1, __shfl_xor_sync(0xFFFFFFFF, mrow1, 2));
        float mnew0 = fmaxf(m_run[0], mrow0);
        float mnew1 = fmaxf(m_run[1], mrow1);
        float alpha0 = ex2(m_run[0] - mnew0);
        float alpha1 = ex2(m_run[1] - mnew1);
        float p[4][4];
        float rs0 = 0.f, rs1 = 0.f;
#pragma unroll
        for (int j = 0; j < 4; j++) {
            p[j][0] = ex2(v[j][0] - mnew0); p[j][1] = ex2(v[j][1] - mnew0);
            p[j][2] = ex2(v[j][2] - mnew1); p[j][3] = ex2(v[j][3] - mnew1);
            rs0 += p[j][0] + p[j][1];
            rs1 += p[j][2] + p[j][3];
        }
        rs0 += __shfl_xor_sync(0xFFFFFFFF, rs0, 1);
        rs0 += __shfl_xor_sync(0xFFFFFFFF, rs0, 2);
        rs1 += __shfl_xor_sync(0xFFFFFFFF, rs1, 1);
        rs1 += __shfl_xor_sync(0xFFFFFFFF, rs1, 2);
        l_run[0] = l_run[0] * alpha0 + rs0;
        l_run[1] = l_run[1] * alpha1 + rs1;
        m_run[0] = mnew0;
        m_run[1] = mnew1;
#pragma unroll
        for (int jj = 0; jj < 16; jj++) {
            o_acc[jj][0] *= alpha0; o_acc[jj][1] *= alpha0;
            o_acc[jj][2] *= alpha1; o_acc[jj][3] *= alpha1;
        }

        uint32_t pa[2][4];
#pragma unroll
        for (int t = 0; t < 2; t++) {
            pa[t][0] = f22u(p[2*t][0],   p[2*t][1]);
            pa[t][1] = f22u(p[2*t][2],   p[2*t][3]);
            pa[t][2] = f22u(p[2*t+1][0], p[2*t+1][1]);
            pa[t][3] = f22u(p[2*t+1][2], p[2*t+1][3]);
        }

#pragma unroll
        for (int g = 0; g < 8; g++) {
#pragma unroll
            for (int t = 0; t < 2; t++) {
                uint32_t vb[4];
                ldsm4(vb, st + 8192 + swoff(16 * g + fr_row, t * 2 + fr_ch));
                mma16816(o_acc[2 * g + 0], pa[t], vb[0], vb[2]);
                mma16816(o_acc[2 * g + 1], pa[t], vb[1], vb[3]);
            }
        }

        if (kt + 2 < nkt) {
            __syncthreads();
            load_stage(kt + 2);
            CP_COMMIT();
        }
    }

    float inv0 = 1.0f / l_run[0];
    float inv1 = 1.0f / l_run[1];
    int b = bh >> 4, h = bh & 15;
    int sg0 = qt * 128 + wm + tr;
#pragma unroll
    for (int jj = 0; jj < 16; jj++) {
        int dcol = jj * 8 + tq * 2;
        size_t a0 = ((size_t)(b * Sdim + sg0)) * Hdim + h * 128 + dcol;
        size_t a1 = ((size_t)(b * Sdim + sg0 + 8)) * Hdim + h * 128 + dcol;
        *(__half2*)(g_ctxh + a0) = __floats2half2_rn(o_acc[jj][0] * inv0, o_acc[jj][1] * inv0);
        *(__half2*)(g_ctxh + a1) = __floats2half2_rn(o_acc[jj][2] * inv1, o_acc[jj][3] * inv1);
    }
}

// ============================ mask passthrough ============================
__global__ void mask_kernel(const unsigned char* __restrict__ m, float* __restrict__ o, int n) {
    int i = blockIdx.x * blockDim.x + threadIdx.x;
    if (i < n) o[i] = m[i] ? 1.0f : 0.0f;
}

// ============================ launch ============================
extern "C" void kernel_launch(void* const* d_in, const int* in_sizes, int n_in,
                              void* d_out, int out_size) {
    const float* hs            = (const float*)d_in[0];
    const unsigned char* mask  = (const unsigned char*)d_in[1];
    const float* ln1w          = (const float*)d_in[2];
    const float* ln1b          = (const float*)d_in[3];
    const float* wqkv          = (const float*)d_in[4];
    const float* bqkv          = (const float*)d_in[5];
    const float* wdense        = (const float*)d_in[6];
    const float* bdense        = (const float*)d_in[7];
    const float* ln2w          = (const float*)d_in[8];
    const float* ln2b          = (const float*)d_in[9];
    const float* w1            = (const float*)d_in[10];
    const float* b1            = (const float*)d_in[11];
    const float* w2            = (const float*)d_in[12];
    const float* b2            = (const float*)d_in[13];
    float* out = (float*)d_out;

    float *phid;
    __half *pxh, *pctxh, *pinterh, *pqkvh, *pwqkvh, *pwdh, *pw1h, *pw2h;
    cudaGetSymbolAddress((void**)&phid,   g_hidden);
    cudaGetSymbolAddress((void**)&pxh,    g_xh);
    cudaGetSymbolAddress((void**)&pctxh,  g_ctxh);
    cudaGetSymbolAddress((void**)&pinterh, g_interh);
    cudaGetSymbolAddress((void**)&pqkvh,  g_qkvh);
    cudaGetSymbolAddress((void**)&pwqkvh, g_wqkvh);
    cudaGetSymbolAddress((void**)&pwdh,   g_wdh);
    cudaGetSymbolAddress((void**)&pw1h,   g_w1h);
    cudaGetSymbolAddress((void**)&pw2h,   g_w2h);

    cudaFuncSetAttribute(attn_kernel, cudaFuncAttributeMaxDynamicSharedMemorySize, AT_SMEM);
    cudaFuncSetAttribute(hgemm<3>, cudaFuncAttributeMaxDynamicSharedMemorySize, HM_SMEM);
    cudaFuncSetAttribute(hgemm_h<1>, cudaFuncAttributeMaxDynamicSharedMemorySize, H2_SMEM);
    cudaFuncSetAttribute(hgemm_h<2>, cudaFuncAttributeMaxDynamicSharedMemorySize, H2_SMEM);

    // weight prep: fp32 -> fp16 (vectorized)
    cvt_kernel<<<(3*Hdim*Hdim/8 + 255)/256, 256>>>(wqkv, pwqkvh, 3*Hdim*Hdim/8);
    cvt_kernel<<<(Hdim*Hdim/8   + 255)/256, 256>>>(wdense, pwdh, Hdim*Hdim/8);
    cvt_kernel<<<(FFdim*Hdim/8  + 255)/256, 256>>>(w1,     pw1h, FFdim*Hdim/8);
    cvt_kernel<<<(Hdim*FFdim/8  + 255)/256, 256>>>(w2,     pw2h, Hdim*FFdim/8);
    // LN1 -> xh
    ln_kernel<<<Mrows, 256>>>(hs, ln1w, ln1b, pxh);
    // RoPE trig table
    rope_table_kernel<<<(Sdim * 64) / 256, 256>>>();
    // QKV = x @ wqkv^T + bqkv (half out, fp32 acc)
    hgemm<3><<<dim3(3 * Hdim / GBN, Mrows / GBM), 512, HM_SMEM>>>(
        pxh, pwqkvh, bqkv, nullptr, nullptr, pqkvh, Mrows, 3 * Hdim, Hdim);
    // split + rope -> qh/kh/vh (half, [B,NH,S,D])
    rope_kernel<<<dim3(Mrows, NHdim), 128>>>();
    // V transpose -> vt (half, [B,NH,D,S])
    vt_kernel<<<dim3(Sdim / 64, Ddim / 64, Bdim * NHdim), 256>>>();
    // HMMA flash attention -> ctxh
    attn_kernel<<<dim3(Sdim / 128, Bdim * NHdim), 256, AT_SMEM>>>();
    // dense + residual(hidden_states) -> g_hidden (fp16-acc probe)
    hgemm_h<2><<<dim3(Hdim / 128, Mrows / 128), 512, H2_SMEM>>>(
        pctxh, pwdh, bdense, hs, phid, nullptr, Mrows, Hdim, Hdim);
    // LN2 -> xh
    ln_kernel<<<Mrows, 256>>>(phid, ln2w, ln2b, pxh);
    // FF1 + GELU -> interh (fp16-acc probe)
    hgemm_h<1><<<dim3(FFdim / 128, Mrows / 128), 512, H2_SMEM>>>(
        pxh, pw1h, b1, nullptr, nullptr, pinterh, Mrows, FFdim, Hdim);
    // FF2 + residual(g_hidden) -> out (fp16-acc probe)
    hgemm_h<2><<<dim3(Hdim / 128, Mrows / 128), 512, H2_SMEM>>>(
        pinterh, pw2h, b2, phid, out, nullptr, Mrows, Hdim, FFdim);
    // if output also carries the attention mask, convert it after hidden
    long long hid_elems = (long long)Mrows * Hdim;           // 8388608
    long long mask_elems = (long long)Sdim * Sdim;           // 4194304
    if ((long long)out_size >= hid_elems + mask_elems) {
        mask_kernel<<<(int)(mask_elems / 256), 256>>>(mask, out + hid_elems, (int)mask_elems);
    }
}

// round 12
// speedup vs baseline: 1.1155x; 1.1155x over previous
#include <cuda_runtime.h>
#include <cuda_fp16.h>
#include <cstdint>
#include <stdint.h>
#include <math.h>

// Problem constants
#define Bdim 2
#define Sdim 2048
#define Hdim 2048
#define NHdim 16
#define Ddim 128
#define FFdim 8192
#define Mrows (Bdim*Sdim)   // 4096

// -------- scratch (device globals; no allocation) --------
__device__ float g_hidden[(size_t)Mrows*Hdim];   // residual+attn_out
__device__ float g_cos[Sdim*64];
__device__ float g_sin[Sdim*64];
__device__ __half g_qkvh[(size_t)Mrows*3*Hdim];  // QKV gemm out (half)
__device__ __half g_qh[(size_t)Mrows*Hdim];      // [B,NH,S,D]
__device__ __half g_kh[(size_t)Mrows*Hdim];
__device__ __half g_vh[(size_t)Mrows*Hdim];
__device__ __half g_vt[(size_t)Mrows*Hdim];      // [B,NH,D,S]
__device__ __half g_xh[(size_t)Mrows*Hdim];
__device__ __half g_ctxh[(size_t)Mrows*Hdim];
__device__ __half g_interh[(size_t)Mrows*FFdim];
__device__ __half g_wqkvh[(size_t)3*Hdim*Hdim];
__device__ __half g_wdh[(size_t)Hdim*Hdim];
__device__ __half g_w1h[(size_t)FFdim*Hdim];
__device__ __half g_w2h[(size_t)Hdim*FFdim];

// ============================ helpers ============================
__device__ __forceinline__ uint32_t smem_u32(const void* p) {
    uint32_t a;
    asm("{ .reg .u64 t; cvta.to.shared.u64 t, %1; cvt.u32.u64 %0, t; }" : "=r"(a) : "l"(p));
    return a;
}
__device__ __forceinline__ void ldsm4(uint32_t* r, uint32_t addr) {
    asm volatile("ldmatrix.sync.aligned.m8n8.x4.shared.b16 {%0,%1,%2,%3}, [%4];"
        : "=r"(r[0]), "=r"(r[1]), "=r"(r[2]), "=r"(r[3]) : "r"(addr));
}
__device__ __forceinline__ void mma16816(float* c, const uint32_t* a, uint32_t b0, uint32_t b1) {
    asm("mma.sync.aligned.m16n8k16.row.col.f32.f16.f16.f32 "
        "{%0,%1,%2,%3}, {%4,%5,%6,%7}, {%8,%9}, {%0,%1,%2,%3};"
        : "+f"(c[0]), "+f"(c[1]), "+f"(c[2]), "+f"(c[3])
        : "r"(a[0]), "r"(a[1]), "r"(a[2]), "r"(a[3]), "r"(b0), "r"(b1));
}
__device__ __forceinline__ void cp16(uint32_t dst, const void* src) {
    asm volatile("cp.async.cg.shared.global [%0], [%1], 16;"
        :: "r"(dst), "l"(__cvta_generic_to_global(src)) : "memory");
}
#define CP_COMMIT() asm volatile("cp.async.commit_group;" ::: "memory")
#define CP_WAIT(n)  asm volatile("cp.async.wait_group %0;" :: "n"(n) : "memory")

__device__ __forceinline__ float ex2(float x) {
    float r;
    asm("ex2.approx.ftz.f32 %0, %1;" : "=f"(r) : "f"(x));
    return r;
}
__device__ __forceinline__ uint32_t f22u(float a, float b) {
    __half2 h = __floats2half2_rn(a, b);
    return *(uint32_t*)&h;
}

// swizzled smem offset: rows of 64B (32 halfs), 16B chunk XOR (row>>1)&3
__device__ __forceinline__ uint32_t swoff(int row, int chunk) {
    return (uint32_t)(row * 64 + ((chunk ^ ((row >> 1) & 3)) << 4));
}

// ============================ weight convert kernel (float4 vectorized) ============================
__global__ void cvt_kernel(const float* __restrict__ in, __half* __restrict__ hi, int n8) {
    int i = blockIdx.x * blockDim.x + threadIdx.x;
    if (i >= n8) return;
    float4 a = ((const float4*)in)[(size_t)i * 2];
    float4 b = ((const float4*)in)[(size_t)i * 2 + 1];
    __half2 h0 = __floats2half2_rn(a.x, a.y), h1 = __floats2half2_rn(a.z, a.w);
    __half2 h2 = __floats2half2_rn(b.x, b.y), h3 = __floats2half2_rn(b.z, b.w);
    ((uint4*)hi)[i] = make_uint4(*(uint32_t*)&h0, *(uint32_t*)&h1,
                                 *(uint32_t*)&h2, *(uint32_t*)&h3);
}

// ============================ HMMA GEMM (fp32 acc, 256x128 tile) — R10 proven ============================
// EPI: 1 = bias+GELU -> Ch half ; 2 = bias+residual -> C fp32 ; 3 = bias -> Ch half
#define GBM 256
#define GBN 128
#define NSTAGE 3
#define STAGE1 24576     // Ah 16K | Wh 8K
#define HM_SMEM (NSTAGE*STAGE1)

template<int EPI>
__global__ void __launch_bounds__(512, 1) hgemm(
    const __half* __restrict__ Ah_, const __half* __restrict__ Wh_,
    const float* __restrict__ bias, const float* __restrict__ res,
    float* __restrict__ C, __half* __restrict__ Ch,
    int M, int N, int K)
{
    extern __shared__ char sm[];
    uint32_t smb = smem_u32(sm);
    int tid = threadIdx.x;
    int lane = tid & 31, wid = tid >> 5;
    int wm = (wid & 3) * 64;
    int wn = (wid >> 2) * 32;
    int bm = blockIdx.y * GBM, bn = blockIdx.x * GBN;

    int aidx = tid * 2;
    int arow = aidx >> 2, ach = aidx & 3;
    int wrow = tid >> 2, wch = tid & 3;
    const __half* pAh = Ah_ + (size_t)(bm + arow) * K + ach * 8;
    const __half* pWh = Wh_ + (size_t)(bn + wrow) * K + wch * 8;
    uint32_t dA0 = swoff(arow, ach), dA1 = swoff(arow, ach + 1);
    uint32_t dW  = swoff(wrow, wch);

    float acc[4][4][4];
#pragma unroll
    for (int i = 0; i < 4; i++)
#pragma unroll
        for (int j = 0; j < 4; j++)
#pragma unroll
            for (int q = 0; q < 4; q++) acc[i][j][q] = 0.f;

    int mat = lane >> 3, mr = lane & 7;
    int fr_row = (mat & 1) * 8 + mr;
    int fr_ch  = mat >> 1;

    const int NC = K >> 5;

    auto load_stage = [&](int c) {
        uint32_t base = smb + (uint32_t)(c % NSTAGE) * STAGE1;
        size_t ko = (size_t)c * 32;
        cp16(base + 0     + dA0, pAh + ko);
        cp16(base + 0     + dA1, pAh + ko + 8);
        cp16(base + 16384 + dW,  pWh + ko);
    };

#pragma unroll
    for (int c = 0; c < NSTAGE - 1; c++) { load_stage(c); CP_COMMIT(); }

    for (int c = 0; c < NC; c++) {
        CP_WAIT(NSTAGE - 2);
        __syncthreads();
        if (c + NSTAGE - 1 < NC) { load_stage(c + NSTAGE - 1); }
        CP_COMMIT();

        uint32_t base = smb + (uint32_t)(c % NSTAGE) * STAGE1;
#pragma unroll
        for (int kk = 0; kk < 2; kk++) {
            uint32_t ah[4][4], bh[2][4];
#pragma unroll
            for (int i = 0; i < 4; i++) {
                uint32_t off = swoff(wm + i * 16 + fr_row, kk * 2 + fr_ch);
                ldsm4(ah[i], base + 0 + off);
            }
#pragma unroll
            for (int g = 0; g < 2; g++) {
                uint32_t off = swoff(wn + g * 16 + fr_row, kk * 2 + fr_ch);
                ldsm4(bh[g], base + 16384 + off);
            }
#pragma unroll
            for (int i = 0; i < 4; i++) {
#pragma unroll
                for (int jj = 0; jj < 4; jj++) {
                    int g = jj >> 1, h = jj & 1;
                    mma16816(acc[i][jj], ah[i], bh[g][h], bh[g][h+2]);
                }
            }
        }
    }

    int tr = lane >> 2;
    int tc = (lane & 3) * 2;
#pragma unroll
    for (int i = 0; i < 4; i++) {
#pragma unroll
        for (int jj = 0; jj < 4; jj++) {
            int n0 = bn + wn + jj * 8 + tc;
            float b0 = bias[n0], b1 = bias[n0 + 1];
#pragma unroll
            for (int half = 0; half < 2; half++) {
                int m = bm + wm + i * 16 + tr + half * 8;
                size_t idx = (size_t)m * N + n0;
                float v0 = acc[i][jj][half * 2 + 0] + b0;
                float v1 = acc[i][jj][half * 2 + 1] + b1;
                if (EPI == 1) {
                    v0 = 0.5f * v0 * (1.0f + erff(v0 * 0.70710678118654752f));
                    v1 = 0.5f * v1 * (1.0f + erff(v1 * 0.70710678118654752f));
                    *(__half2*)(Ch + idx) = __floats2half2_rn(v0, v1);
                } else if (EPI == 3) {
                    *(__half2*)(Ch + idx) = __floats2half2_rn(v0, v1);
                } else {
                    if (EPI == 2) { v0 += res[idx]; v1 += res[idx + 1]; }
                    *(float2*)(C + idx) = make_float2(v0, v1);
                }
            }
        }
    }
}

// ============================ LayerNorm -> fp16 ============================
__global__ void ln_kernel(const float* __restrict__ in, const float* __restrict__ w,
                          const float* __restrict__ b, __half* __restrict__ oh) {
    __shared__ float2 red[256];
    int row = blockIdx.x;
    const float* x = in + (size_t)row * Hdim;
    float s = 0.f, ss = 0.f;
    for (int i = threadIdx.x * 2; i < Hdim; i += 512) {
        float2 v = *(const float2*)(x + i);
        s += v.x + v.y;
        ss = fmaf(v.x, v.x, fmaf(v.y, v.y, ss));
    }
    red[threadIdx.x] = make_float2(s, ss);
    __syncthreads();
    for (int o = 128; o > 0; o >>= 1) {
        if (threadIdx.x < o) {
            float2 a = red[threadIdx.x], c = red[threadIdx.x + o];
            red[threadIdx.x] = make_float2(a.x + c.x, a.y + c.y);
        }
        __syncthreads();
    }
    float mean = red[0].x * (1.0f / Hdim);
    float var  = red[0].y * (1.0f / Hdim) - mean * mean;
    float rstd = rsqrtf(var + 1e-5f);
    for (int i = threadIdx.x * 2; i < Hdim; i += 512) {
        float2 v = *(const float2*)(x + i);
        float2 wv = *(const float2*)(w + i);
        float2 bv = *(const float2*)(b + i);
        float o0 = (v.x - mean) * rstd * wv.x + bv.x;
        float o1 = (v.y - mean) * rstd * wv.y + bv.y;
        *(__half2*)(oh + (size_t)row * Hdim + i) = __floats2half2_rn(o0, o1);
    }
}

// ============================ RoPE table (double precision trig) ============================
__global__ void rope_table_kernel() {
    int idx = blockIdx.x * blockDim.x + threadIdx.x;
    if (idx >= Sdim * 64) return;
    int s = idx >> 6, i = idx & 63;
    double invf = exp(-(double)i * (9.210340371976184 / 64.0)); // ln(10000)/64
    double th = (double)s * invf;
    g_cos[idx] = (float)cos(th);
    g_sin[idx] = (float)sin(th);
}

// ============================ QKV split + RoPE (half in, half out) ============================
__global__ void rope_kernel() {
    int row = blockIdx.x;      // b*S + s
    int h = blockIdx.y;
    int d = threadIdx.x;       // 0..127
    int s = row & (Sdim - 1);
    int b = row >> 11;
    const __half* src = g_qkvh + (size_t)row * (3 * Hdim) + h * (3 * Ddim);
    float q = __half2float(src[d]);
    float k = __half2float(src[Ddim + d]);
    __half v = src[2 * Ddim + d];
    int di = d & 63;
    float cs = g_cos[s * 64 + di];
    float sn = g_sin[s * 64 + di];
    float qp, kp;
    if (d < 64) { qp = -__half2float(src[d + 64]);      kp = -__half2float(src[Ddim + d + 64]); }
    else        { qp =  __half2float(src[d - 64]);      kp =  __half2float(src[Ddim + d - 64]); }
    size_t oidx = ((size_t)(b * NHdim + h) * Sdim + s) * Ddim + d;
    g_qh[oidx] = __float2half(q * cs + qp * sn);
    g_kh[oidx] = __float2half(k * cs + kp * sn);
    g_vh[oidx] = v;
}

// ============================ V transpose: [bh,S,D] -> [bh,D,S] ============================
__global__ void vt_kernel() {
    __shared__ __half tile[64][66];
    int bh = blockIdx.z;
    int s0 = blockIdx.x * 64, d0 = blockIdx.y * 64;
    const __half* src = g_vh + ((size_t)bh * Sdim + s0) * Ddim + d0;
#pragma unroll
    for (int i = 0; i < 16; i++) {
        int idx = threadIdx.x + i * 256;
        int r = idx >> 6, c = idx & 63;
        tile[r][c] = src[(size_t)r * Ddim + c];
    }
    __syncthreads();
    __half* dst = g_vt + ((size_t)bh * Ddim + d0) * Sdim + s0;
#pragma unroll
    for (int i = 0; i < 16; i++) {
        int idx = threadIdx.x + i * 256;
        int dr = idx >> 6, sc = idx & 63;
        dst[(size_t)dr * Sdim + sc] = tile[sc][dr];
    }
}

// ============================ HMMA flash attention (causal, Bc=64) ============================
// Br=128, Bc=64, 8 warps. Q frags register-resident; P frags from S accums in place.
// stage = K 16KB (4 kb-blocks of 64rows x 64B) + VT 16KB (2 sub-tiles of 128rows x 64B)
#define AT_STAGE 32768
#define AT_SMEM (32768 + 2*AT_STAGE)

__global__ void __launch_bounds__(256, 1) attn_kernel() {
    extern __shared__ char sm[];
    uint32_t smb = smem_u32(sm);
    uint32_t qbase = smb;
    int tid = threadIdx.x;
    int lane = tid & 31, wid = tid >> 5;
    int qt = gridDim.x - 1 - blockIdx.x;
    int bh = blockIdx.y;

    const __half* Qg  = g_qh + ((size_t)bh * Sdim + (size_t)qt * 128) * Ddim;
    const __half* Kg  = g_kh + (size_t)bh * Sdim * Ddim;
    const __half* VTg = g_vt + (size_t)bh * Ddim * Sdim;

    // ---- Q load (8 cp16/thread) ----
    {
        int row = tid >> 1, kb0 = (tid & 1) * 2;
#pragma unroll
        for (int i = 0; i < 8; i++) {
            int kb = kb0 + (i >> 2), ch = i & 3;
            cp16(qbase + kb * 8192 + swoff(row, ch), Qg + (size_t)row * 128 + kb * 32 + ch * 8);
        }
    }
    // stage for 64 K-rows: K at st (kb*4096 blocks, 64 rows x 64B), VT at st+16384 (vs*8192)
    auto load_stage = [&](int kt) {
        uint32_t st = smb + 32768 + (uint32_t)(kt & 1) * AT_STAGE;
        const __half* kp = Kg + (size_t)kt * 64 * 128;
#pragma unroll
        for (int i = 0; i < 4; i++) {
            int idx = tid + i * 256;
            int krow = idx >> 4, kb = (idx >> 2) & 3, ch = idx & 3;
            cp16(st + kb * 4096 + swoff(krow, ch), kp + (size_t)krow * 128 + kb * 32 + ch * 8);
        }
        const __half* vp = VTg + (size_t)kt * 64;
#pragma unroll
        for (int i = 0; i < 4; i++) {
            int idx = tid + i * 256;
            int vs = idx >> 9, drow = (idx >> 2) & 127, ch = idx & 3;
            cp16(st + 16384 + vs * 8192 + swoff(drow, ch),
                 vp + (size_t)drow * Sdim + vs * 32 + ch * 8);
        }
    };

    int nkt = 2 * qt + 2;
    load_stage(0); CP_COMMIT();
    if (nkt > 1) { load_stage(1); } CP_COMMIT();
    CP_WAIT(1);
    __syncthreads();

    int mat = lane >> 3, mr = lane & 7;
    int fr_row = (mat & 1) * 8 + mr, fr_ch = mat >> 1;
    int wm = wid * 16;
    int tr = lane >> 2, tq = lane & 3;

    uint32_t qf[8][4];
#pragma unroll
    for (int kk = 0; kk < 8; kk++)
        ldsm4(qf[kk], qbase + (kk >> 1) * 8192 + swoff(wm + fr_row, (kk & 1) * 2 + fr_ch));

    float o_acc[16][4];
#pragma unroll
    for (int j = 0; j < 16; j++)
#pragma unroll
        for (int q = 0; q < 4; q++) o_acc[j][q] = 0.f;
    float m_run[2] = { -INFINITY, -INFINITY };
    float l_run[2] = { 0.f, 0.f };

    const float SC = 0.08838834764831845f * 1.4426950408889634f;
    int rowg0 = qt * 128 + wm + tr;

    for (int kt = 0; kt < nkt; kt++) {
        if (kt > 0) { CP_WAIT(1); __syncthreads(); }
        uint32_t st = smb + 32768 + (uint32_t)(kt & 1) * AT_STAGE;

        // ---- S = Q K^T over 64 cols: 8 n8 accumulators ----
        float s_acc[8][4];
#pragma unroll
        for (int j = 0; j < 8; j++)
#pragma unroll
            for (int q = 0; q < 4; q++) s_acc[j][q] = 0.f;
#pragma unroll
        for (int kk = 0; kk < 8; kk++) {
            uint32_t kf[4][4];
#pragma unroll
            for (int g = 0; g < 4; g++)
                ldsm4(kf[g], st + (kk >> 1) * 4096 + swoff(16 * g + fr_row, (kk & 1) * 2 + fr_ch));
#pragma unroll
            for (int g = 0; g < 4; g++)
#pragma unroll
                for (int h = 0; h < 2; h++)
                    mma16816(s_acc[2 * g + h], qf[kk], kf[g][h], kf[g][h + 2]);
        }

        // ---- mask + scale in place, then softmax ----
#pragma unroll
        for (int j = 0; j < 8; j++)
#pragma unroll
            for (int q = 0; q < 4; q++) {
                int colg = kt * 64 + j * 8 + tq * 2 + (q & 1);
                int rowg = rowg0 + (q >> 1) * 8;
                float x = s_acc[j][q] * SC;
                s_acc[j][q] = (colg <= rowg) ? x : -1e30f;
            }
        float mrow0 = -1e30f, mrow1 = -1e30f;
#pragma unroll
        for (int j = 0; j < 8; j++) {
            mrow0 = fmaxf(mrow0, fmaxf(s_acc[j][0], s_acc[j][1]));
            mrow1 = fmaxf(mrow1, fmaxf(s_acc[j][2], s_acc[j][3]));
        }
        mrow0 = fmaxf(mrow0, __shfl_xor_sync(0xFFFFFFFF, mrow0, 1));
        mrow0 = fmaxf(mrow0, __shfl_xor_sync(0xFFFFFFFF, mrow0, 2));
        mrow1 = fmaxf(mrow1, __shfl_xor_sync(0xFFFFFFFF, mrow1, 1));
        mrow1 = fmaxf(mrow1, __shfl_xor_sync(0xFFFFFFFF, mrow1, 2));
        float mnew0 = fmaxf(m_run[0], mrow0);
        float mnew1 = fmaxf(m_run[1], mrow1);
        float alpha0 = ex2(m_run[0] - mnew0);
        float alpha1 = ex2(m_run[1] - mnew1);
        float rs0 = 0.f, rs1 = 0.f;
#pragma unroll
        for (int j = 0; j < 8; j++) {
            s_acc[j][0] = ex2(s_acc[j][0] - mnew0);
            s_acc[j][1] = ex2(s_acc[j][1] - mnew0);
            s_acc[j][2] = ex2(s_acc[j][2] - mnew1);
            s_acc[j][3] = ex2(s_acc[j][3] - mnew1);
            rs0 += s_acc[j][0] + s_acc[j][1];
            rs1 += s_acc[j][2] + s_acc[j][3];
        }
        rs0 += __shfl_xor_sync(0xFFFFFFFF, rs0, 1);
        rs0 += __shfl_xor_sync(0xFFFFFFFF, rs0, 2);
        rs1 += __shfl_xor_sync(0xFFFFFFFF, rs1, 1);
        rs1 += __shfl_xor_sync(0xFFFFFFFF, rs1, 2);
        l_run[0] = l_run[0] * alpha0 + rs0;
        l_run[1] = l_run[1] * alpha1 + rs1;
        m_run[0] = mnew0;
        m_run[1] = mnew1;
#pragma unroll
        for (int jj = 0; jj < 16; jj++) {
            o_acc[jj][0] *= alpha0; o_acc[jj][1] *= alpha0;
            o_acc[jj][2] *= alpha1; o_acc[jj][3] *= alpha1;
        }

        // ---- P fragments: 2 vs-halves x 2 k16 frags each ----
        uint32_t pa[2][2][4];
#pragma unroll
        for (int vs = 0; vs < 2; vs++)
#pragma unroll
            for (int t = 0; t < 2; t++) {
                int j0 = vs * 4 + 2 * t;
                pa[vs][t][0] = f22u(s_acc[j0][0],   s_acc[j0][1]);
                pa[vs][t][1] = f22u(s_acc[j0][2],   s_acc[j0][3]);
                pa[vs][t][2] = f22u(s_acc[j0+1][0], s_acc[j0+1][1]);
                pa[vs][t][3] = f22u(s_acc[j0+1][2], s_acc[j0+1][3]);
            }

        // ---- O += P V (2 vs-halves of 32 k each) ----
#pragma unroll
        for (int vs = 0; vs < 2; vs++) {
#pragma unroll
            for (int g = 0; g < 8; g++) {
#pragma unroll
                for (int t = 0; t < 2; t++) {
                    uint32_t vb[4];
                    ldsm4(vb, st + 16384 + vs * 8192 + swoff(16 * g + fr_row, t * 2 + fr_ch));
                    mma16816(o_acc[2 * g + 0], pa[vs][t], vb[0], vb[2]);
                    mma16816(o_acc[2 * g + 1], pa[vs][t], vb[1], vb[3]);
                }
            }
        }

        if (kt + 2 < nkt) {
            __syncthreads();
            load_stage(kt + 2);
            CP_COMMIT();
        } else {
            CP_COMMIT();   // keep group count in sync for CP_WAIT(1)
        }
    }

    // ---- epilogue ----
    float inv0 = 1.0f / l_run[0];
    float inv1 = 1.0f / l_run[1];
    int b = bh >> 4, h = bh & 15;
    int sg0 = qt * 128 + wm + tr;
#pragma unroll
    for (int jj = 0; jj < 16; jj++) {
        int dcol = jj * 8 + tq * 2;
        size_t a0 = ((size_t)(b * Sdim + sg0)) * Hdim + h * 128 + dcol;
        size_t a1 = ((size_t)(b * Sdim + sg0 + 8)) * Hdim + h * 128 + dcol;
        *(__half2*)(g_ctxh + a0) = __floats2half2_rn(o_acc[jj][0] * inv0, o_acc[jj][1] * inv0);
        *(__half2*)(g_ctxh + a1) = __floats2half2_rn(o_acc[jj][2] * inv1, o_acc[jj][3] * inv1);
    }
}

// ============================ mask passthrough ============================
__global__ void mask_kernel(const unsigned char* __restrict__ m, float* __restrict__ o, int n) {
    int i = blockIdx.x * blockDim.x + threadIdx.x;
    if (i < n) o[i] = m[i] ? 1.0f : 0.0f;
}

// ============================ launch ============================
extern "C" void kernel_launch(void* const* d_in, const int* in_sizes, int n_in,
                              void* d_out, int out_size) {
    const float* hs            = (const float*)d_in[0];
    const unsigned char* mask  = (const unsigned char*)d_in[1];
    const float* ln1w          = (const float*)d_in[2];
    const float* ln1b          = (const float*)d_in[3];
    const float* wqkv          = (const float*)d_in[4];
    const float* bqkv          = (const float*)d_in[5];
    const float* wdense        = (const float*)d_in[6];
    const float* bdense        = (const float*)d_in[7];
    const float* ln2w          = (const float*)d_in[8];
    const float* ln2b          = (const float*)d_in[9];
    const float* w1            = (const float*)d_in[10];
    const float* b1            = (const float*)d_in[11];
    const float* w2            = (const float*)d_in[12];
    const float* b2            = (const float*)d_in[13];
    float* out = (float*)d_out;

    float *phid;
    __half *pxh, *pctxh, *pinterh, *pqkvh, *pwqkvh, *pwdh, *pw1h, *pw2h;
    cudaGetSymbolAddress((void**)&phid,   g_hidden);
    cudaGetSymbolAddress((void**)&pxh,    g_xh);
    cudaGetSymbolAddress((void**)&pctxh,  g_ctxh);
    cudaGetSymbolAddress((void**)&pinterh, g_interh);
    cudaGetSymbolAddress((void**)&pqkvh,  g_qkvh);
    cudaGetSymbolAddress((void**)&pwqkvh, g_wqkvh);
    cudaGetSymbolAddress((void**)&pwdh,   g_wdh);
    cudaGetSymbolAddress((void**)&pw1h,   g_w1h);
    cudaGetSymbolAddress((void**)&pw2h,   g_w2h);

    cudaFuncSetAttribute(attn_kernel, cudaFuncAttributeMaxDynamicSharedMemorySize, AT_SMEM);
    cudaFuncSetAttribute(hgemm<1>, cudaFuncAttributeMaxDynamicSharedMemorySize, HM_SMEM);
    cudaFuncSetAttribute(hgemm<2>, cudaFuncAttributeMaxDynamicSharedMemorySize, HM_SMEM);
    cudaFuncSetAttribute(hgemm<3>, cudaFuncAttributeMaxDynamicSharedMemorySize, HM_SMEM);

    // weight prep: fp32 -> fp16 (vectorized)
    cvt_kernel<<<(3*Hdim*Hdim/8 + 255)/256, 256>>>(wqkv, pwqkvh, 3*Hdim*Hdim/8);
    cvt_kernel<<<(Hdim*Hdim/8   + 255)/256, 256>>>(wdense, pwdh, Hdim*Hdim/8);
    cvt_kernel<<<(FFdim*Hdim/8  + 255)/256, 256>>>(w1,     pw1h, FFdim*Hdim/8);
    cvt_kernel<<<(Hdim*FFdim/8  + 255)/256, 256>>>(w2,     pw2h, Hdim*FFdim/8);
    // LN1 -> xh
    ln_kernel<<<Mrows, 256>>>(hs, ln1w, ln1b, pxh);
    // RoPE trig table
    rope_table_kernel<<<(Sdim * 64) / 256, 256>>>();
    // QKV = x @ wqkv^T + bqkv (half out, fp32 acc)
    hgemm<3><<<dim3(3 * Hdim / GBN, Mrows / GBM), 512, HM_SMEM>>>(
        pxh, pwqkvh, bqkv, nullptr, nullptr, pqkvh, Mrows, 3 * Hdim, Hdim);
    // split + rope -> qh/kh/vh (half, [B,NH,S,D])
    rope_kernel<<<dim3(Mrows, NHdim), 128>>>();
    // V transpose -> vt (half, [B,NH,D,S])
    vt_kernel<<<dim3(Sdim / 64, Ddim / 64, Bdim * NHdim), 256>>>();
    // HMMA flash attention (Bc=64) -> ctxh
    attn_kernel<<<dim3(Sdim / 128, Bdim * NHdim), 256, AT_SMEM>>>();
    // dense + residual(hidden_states) -> g_hidden (fp32)
    hgemm<2><<<dim3(Hdim / GBN, Mrows / GBM), 512, HM_SMEM>>>(
        pctxh, pwdh, bdense, hs, phid, nullptr, Mrows, Hdim, Hdim);
    // LN2 -> xh
    ln_kernel<<<Mrows, 256>>>(phid, ln2w, ln2b, pxh);
    // FF1 + GELU -> interh (fp16)
    hgemm<1><<<dim3(FFdim / GBN, Mrows / GBM), 512, HM_SMEM>>>(
        pxh, pw1h, b1, nullptr, nullptr, pinterh, Mrows, FFdim, Hdim);
    // FF2 + residual(g_hidden) -> out
    hgemm<2><<<dim3(Hdim / GBN, Mrows / GBM), 512, HM_SMEM>>>(
        pinterh, pw2h, b2, phid, out, nullptr, Mrows, Hdim, FFdim);
    // if output also carries the attention mask, convert it after hidden
    long long hid_elems = (long long)Mrows * Hdim;           // 8388608
    long long mask_elems = (long long)Sdim * Sdim;           // 4194304
    if ((long long)out_size >= hid_elems + mask_elems) {
        mask_kernel<<<(int)(mask_elems / 256), 256>>>(mask, out + hid_elems, (int)mask_elems);
    }
}

// round 13
// speedup vs baseline: 1.1198x; 1.0038x over previous
#include <cuda_runtime.h>
#include <cuda_fp16.h>
#include <cstdint>
#include <stdint.h>
#include <math.h>

// Problem constants
#define Bdim 2
#define Sdim 2048
#define Hdim 2048
#define NHdim 16
#define Ddim 128
#define FFdim 8192
#define Mrows (Bdim*Sdim)   // 4096

// -------- scratch (device globals; no allocation) --------
__device__ float g_hidden[(size_t)Mrows*Hdim];   // residual+attn_out
__device__ float g_cos[Sdim*64];
__device__ float g_sin[Sdim*64];
__device__ __half g_qkvh[(size_t)Mrows*3*Hdim];  // QKV gemm out (half)
__device__ __half g_qh[(size_t)Mrows*Hdim];      // [B,NH,S,D]
__device__ __half g_kh[(size_t)Mrows*Hdim];
__device__ __half g_vt[(size_t)Mrows*Hdim];      // [B,NH,D,S]
__device__ __half g_xh[(size_t)Mrows*Hdim];
__device__ __half g_ctxh[(size_t)Mrows*Hdim];
__device__ __half g_interh[(size_t)Mrows*FFdim];
__device__ __half g_wqkvh[(size_t)3*Hdim*Hdim];
__device__ __half g_wdh[(size_t)Hdim*Hdim];
__device__ __half g_w1h[(size_t)FFdim*Hdim];
__device__ __half g_w2h[(size_t)Hdim*FFdim];

// ============================ helpers ============================
__device__ __forceinline__ uint32_t smem_u32(const void* p) {
    uint32_t a;
    asm("{ .reg .u64 t; cvta.to.shared.u64 t, %1; cvt.u32.u64 %0, t; }" : "=r"(a) : "l"(p));
    return a;
}
__device__ __forceinline__ void ldsm4(uint32_t* r, uint32_t addr) {
    asm volatile("ldmatrix.sync.aligned.m8n8.x4.shared.b16 {%0,%1,%2,%3}, [%4];"
        : "=r"(r[0]), "=r"(r[1]), "=r"(r[2]), "=r"(r[3]) : "r"(addr));
}
__device__ __forceinline__ void mma16816(float* c, const uint32_t* a, uint32_t b0, uint32_t b1) {
    asm("mma.sync.aligned.m16n8k16.row.col.f32.f16.f16.f32 "
        "{%0,%1,%2,%3}, {%4,%5,%6,%7}, {%8,%9}, {%0,%1,%2,%3};"
        : "+f"(c[0]), "+f"(c[1]), "+f"(c[2]), "+f"(c[3])
        : "r"(a[0]), "r"(a[1]), "r"(a[2]), "r"(a[3]), "r"(b0), "r"(b1));
}
__device__ __forceinline__ void cp16(uint32_t dst, const void* src) {
    asm volatile("cp.async.cg.shared.global [%0], [%1], 16;"
        :: "r"(dst), "l"(__cvta_generic_to_global(src)) : "memory");
}
#define CP_COMMIT() asm volatile("cp.async.commit_group;" ::: "memory")
#define CP_WAIT(n)  asm volatile("cp.async.wait_group %0;" :: "n"(n) : "memory")

__device__ __forceinline__ float ex2(float x) {
    float r;
    asm("ex2.approx.ftz.f32 %0, %1;" : "=f"(r) : "f"(x));
    return r;
}
__device__ __forceinline__ uint32_t f22u(float a, float b) {
    __half2 h = __floats2half2_rn(a, b);
    return *(uint32_t*)&h;
}

// swizzled smem offset: rows of 64B (32 halfs), 16B chunk XOR (row>>1)&3
__device__ __forceinline__ uint32_t swoff(int row, int chunk) {
    return (uint32_t)(row * 64 + ((chunk ^ ((row >> 1) & 3)) << 4));
}

// ============================ weight convert kernel (float4 vectorized) ============================
__global__ void cvt_kernel(const float* __restrict__ in, __half* __restrict__ hi, int n8) {
    int i = blockIdx.x * blockDim.x + threadIdx.x;
    if (i >= n8) return;
    float4 a = ((const float4*)in)[(size_t)i * 2];
    float4 b = ((const float4*)in)[(size_t)i * 2 + 1];
    __half2 h0 = __floats2half2_rn(a.x, a.y), h1 = __floats2half2_rn(a.z, a.w);
    __half2 h2 = __floats2half2_rn(b.x, b.y), h3 = __floats2half2_rn(b.z, b.w);
    ((uint4*)hi)[i] = make_uint4(*(uint32_t*)&h0, *(uint32_t*)&h1,
                                 *(uint32_t*)&h2, *(uint32_t*)&h3);
}

// ============================ HMMA GEMM (fp32 acc, 256x128 tile) ============================
// EPI: 1 = bias+GELU -> Ch half ; 2 = bias+residual -> C fp32 ; 3 = bias -> Ch half
#define GBM 256
#define GBN 128
#define NSTAGE 3
#define STAGE1 24576     // Ah 16K | Wh 8K
#define HM_SMEM (NSTAGE*STAGE1)

template<int EPI>
__global__ void __launch_bounds__(512, 1) hgemm(
    const __half* __restrict__ Ah_, const __half* __restrict__ Wh_,
    const float* __restrict__ bias, const float* __restrict__ res,
    float* __restrict__ C, __half* __restrict__ Ch,
    int M, int N, int K)
{
    extern __shared__ char sm[];
    uint32_t smb = smem_u32(sm);
    int tid = threadIdx.x;
    int lane = tid & 31, wid = tid >> 5;
    int wm = (wid & 3) * 64;
    int wn = (wid >> 2) * 32;
    int bm = blockIdx.y * GBM, bn = blockIdx.x * GBN;

    int aidx = tid * 2;
    int arow = aidx >> 2, ach = aidx & 3;
    int wrow = tid >> 2, wch = tid & 3;
    const __half* pAh = Ah_ + (size_t)(bm + arow) * K + ach * 8;
    const __half* pWh = Wh_ + (size_t)(bn + wrow) * K + wch * 8;
    uint32_t dA0 = swoff(arow, ach), dA1 = swoff(arow, ach + 1);
    uint32_t dW  = swoff(wrow, wch);

    float acc[4][4][4];
#pragma unroll
    for (int i = 0; i < 4; i++)
#pragma unroll
        for (int j = 0; j < 4; j++)
#pragma unroll
            for (int q = 0; q < 4; q++) acc[i][j][q] = 0.f;

    int mat = lane >> 3, mr = lane & 7;
    int fr_row = (mat & 1) * 8 + mr;
    int fr_ch  = mat >> 1;

    const int NC = K >> 5;

    auto load_stage = [&](int c) {
        uint32_t base = smb + (uint32_t)(c % NSTAGE) * STAGE1;
        size_t ko = (size_t)c * 32;
        cp16(base + 0     + dA0, pAh + ko);
        cp16(base + 0     + dA1, pAh + ko + 8);
        cp16(base + 16384 + dW,  pWh + ko);
    };

#pragma unroll
    for (int c = 0; c < NSTAGE - 1; c++) { load_stage(c); CP_COMMIT(); }

    for (int c = 0; c < NC; c++) {
        CP_WAIT(NSTAGE - 2);
        __syncthreads();
        if (c + NSTAGE - 1 < NC) { load_stage(c + NSTAGE - 1); }
        CP_COMMIT();

        uint32_t base = smb + (uint32_t)(c % NSTAGE) * STAGE1;
#pragma unroll
        for (int kk = 0; kk < 2; kk++) {
            uint32_t ah[4][4], bh[2][4];
#pragma unroll
            for (int i = 0; i < 4; i++) {
                uint32_t off = swoff(wm + i * 16 + fr_row, kk * 2 + fr_ch);
                ldsm4(ah[i], base + 0 + off);
            }
#pragma unroll
            for (int g = 0; g < 2; g++) {
                uint32_t off = swoff(wn + g * 16 + fr_row, kk * 2 + fr_ch);
                ldsm4(bh[g], base + 16384 + off);
            }
#pragma unroll
            for (int i = 0; i < 4; i++) {
#pragma unroll
                for (int jj = 0; jj < 4; jj++) {
                    int g = jj >> 1, h = jj & 1;
                    mma16816(acc[i][jj], ah[i], bh[g][h], bh[g][h+2]);
                }
            }
        }
    }

    int tr = lane >> 2;
    int tc = (lane & 3) * 2;
#pragma unroll
    for (int i = 0; i < 4; i++) {
#pragma unroll
        for (int jj = 0; jj < 4; jj++) {
            int n0 = bn + wn + jj * 8 + tc;
            float b0 = bias[n0], b1 = bias[n0 + 1];
#pragma unroll
            for (int half = 0; half < 2; half++) {
                int m = bm + wm + i * 16 + tr + half * 8;
                size_t idx = (size_t)m * N + n0;
                float v0 = acc[i][jj][half * 2 + 0] + b0;
                float v1 = acc[i][jj][half * 2 + 1] + b1;
                if (EPI == 1) {
                    v0 = 0.5f * v0 * (1.0f + erff(v0 * 0.70710678118654752f));
                    v1 = 0.5f * v1 * (1.0f + erff(v1 * 0.70710678118654752f));
                    *(__half2*)(Ch + idx) = __floats2half2_rn(v0, v1);
                } else if (EPI == 3) {
                    *(__half2*)(Ch + idx) = __floats2half2_rn(v0, v1);
                } else {
                    if (EPI == 2) { v0 += res[idx]; v1 += res[idx + 1]; }
                    *(float2*)(C + idx) = make_float2(v0, v1);
                }
            }
        }
    }
}

// ============================ LayerNorm -> fp16 ============================
__global__ void ln_kernel(const float* __restrict__ in, const float* __restrict__ w,
                          const float* __restrict__ b, __half* __restrict__ oh) {
    __shared__ float2 red[256];
    int row = blockIdx.x;
    const float* x = in + (size_t)row * Hdim;
    float s = 0.f, ss = 0.f;
    for (int i = threadIdx.x * 2; i < Hdim; i += 512) {
        float2 v = *(const float2*)(x + i);
        s += v.x + v.y;
        ss = fmaf(v.x, v.x, fmaf(v.y, v.y, ss));
    }
    red[threadIdx.x] = make_float2(s, ss);
    __syncthreads();
    for (int o = 128; o > 0; o >>= 1) {
        if (threadIdx.x < o) {
            float2 a = red[threadIdx.x], c = red[threadIdx.x + o];
            red[threadIdx.x] = make_float2(a.x + c.x, a.y + c.y);
        }
        __syncthreads();
    }
    float mean = red[0].x * (1.0f / Hdim);
    float var  = red[0].y * (1.0f / Hdim) - mean * mean;
    float rstd = rsqrtf(var + 1e-5f);
    for (int i = threadIdx.x * 2; i < Hdim; i += 512) {
        float2 v = *(const float2*)(x + i);
        float2 wv = *(const float2*)(w + i);
        float2 bv = *(const float2*)(b + i);
        float o0 = (v.x - mean) * rstd * wv.x + bv.x;
        float o1 = (v.y - mean) * rstd * wv.y + bv.y;
        *(__half2*)(oh + (size_t)row * Hdim + i) = __floats2half2_rn(o0, o1);
    }
}

// ============================ RoPE table (double precision trig) ============================
__global__ void rope_table_kernel() {
    int idx = blockIdx.x * blockDim.x + threadIdx.x;
    if (idx >= Sdim * 64) return;
    int s = idx >> 6, i = idx & 63;
    double invf = exp(-(double)i * (9.210340371976184 / 64.0)); // ln(10000)/64
    double th = (double)s * invf;
    g_cos[idx] = (float)cos(th);
    g_sin[idx] = (float)sin(th);
}

// ============================ QKV split + RoPE (q,k only; half in/out) ============================
__global__ void rope_kernel() {
    int row = blockIdx.x;      // b*S + s
    int h = blockIdx.y;
    int d = threadIdx.x;       // 0..127
    int s = row & (Sdim - 1);
    int b = row >> 11;
    const __half* src = g_qkvh + (size_t)row * (3 * Hdim) + h * (3 * Ddim);
    float q = __half2float(src[d]);
    float k = __half2float(src[Ddim + d]);
    int di = d & 63;
    float cs = g_cos[s * 64 + di];
    float sn = g_sin[s * 64 + di];
    float qp, kp;
    if (d < 64) { qp = -__half2float(src[d + 64]);      kp = -__half2float(src[Ddim + d + 64]); }
    else        { qp =  __half2float(src[d - 64]);      kp =  __half2float(src[Ddim + d - 64]); }
    size_t oidx = ((size_t)(b * NHdim + h) * Sdim + s) * Ddim + d;
    g_qh[oidx] = __float2half(q * cs + qp * sn);
    g_kh[oidx] = __float2half(k * cs + kp * sn);
}

// ============================ V transpose: qkvh -> [bh,D,S] ============================
__global__ void vt_kernel() {
    __shared__ __half tile[64][66];
    int bh = blockIdx.z;
    int b = bh >> 4, h = bh & 15;
    int s0 = blockIdx.x * 64, d0 = blockIdx.y * 64;
    const __half* src = g_qkvh + (size_t)(b * Sdim + s0) * (3 * Hdim) + h * (3 * Ddim) + 2 * Ddim + d0;
#pragma unroll
    for (int i = 0; i < 16; i++) {
        int idx = threadIdx.x + i * 256;
        int r = idx >> 6, c = idx & 63;
        tile[r][c] = src[(size_t)r * (3 * Hdim) + c];
    }
    __syncthreads();
    __half* dst = g_vt + ((size_t)bh * Ddim + d0) * Sdim + s0;
#pragma unroll
    for (int i = 0; i < 16; i++) {
        int idx = threadIdx.x + i * 256;
        int dr = idx >> 6, sc = idx & 63;
        dst[(size_t)dr * Sdim + sc] = tile[sc][dr];
    }
}

// ============================ HMMA flash attention (causal, Bc=128) ============================
// Br=128, Bc=128, 8 warps. Q frags register-resident; P frags from S accums in place.
// stage = K 32KB (4 kb-blocks of 128rows x 64B) + VT 32KB (4 vs sub-tiles of 128rows x 64B)
#define AT_STAGE 65536
#define AT_SMEM (32768 + 2*AT_STAGE)

__global__ void __launch_bounds__(256, 1) attn_kernel() {
    extern __shared__ char sm[];
    uint32_t smb = smem_u32(sm);
    uint32_t qbase = smb;
    int tid = threadIdx.x;
    int lane = tid & 31, wid = tid >> 5;
    int qt = gridDim.x - 1 - blockIdx.x;
    int bh = blockIdx.y;

    const __half* Qg  = g_qh + ((size_t)bh * Sdim + (size_t)qt * 128) * Ddim;
    const __half* Kg  = g_kh + (size_t)bh * Sdim * Ddim;
    const __half* VTg = g_vt + (size_t)bh * Ddim * Sdim;

    // ---- Q load (8 cp16/thread) ----
    {
        int row = tid >> 1, kb0 = (tid & 1) * 2;
#pragma unroll
        for (int i = 0; i < 8; i++) {
            int kb = kb0 + (i >> 2), ch = i & 3;
            cp16(qbase + kb * 8192 + swoff(row, ch), Qg + (size_t)row * 128 + kb * 32 + ch * 8);
        }
    }
    // stage for 128 K-rows: K at st (kb*8192), VT at st+32768 (vs*8192)
    auto load_stage = [&](int kt) {
        uint32_t st = smb + 32768 + (uint32_t)(kt & 1) * AT_STAGE;
        const __half* kp = Kg + (size_t)kt * 128 * 128;
#pragma unroll
        for (int i = 0; i < 8; i++) {
            int idx = tid + i * 256;
            int krow = idx >> 4, kb = (idx >> 2) & 3, ch = idx & 3;
            cp16(st + kb * 8192 + swoff(krow, ch), kp + (size_t)krow * 128 + kb * 32 + ch * 8);
        }
        const __half* vp = VTg + (size_t)kt * 128;
#pragma unroll
        for (int i = 0; i < 8; i++) {
            int idx = tid + i * 256;
            int vs = idx >> 9, drow = (idx >> 2) & 127, ch = idx & 3;
            cp16(st + 32768 + vs * 8192 + swoff(drow, ch),
                 vp + (size_t)drow * Sdim + vs * 32 + ch * 8);
        }
    };

    int nkt = qt + 1;
    // prologue: always load two stages (stage 1 rows are always within S)
    load_stage(0); CP_COMMIT();
    load_stage(1); CP_COMMIT();
    CP_WAIT(1);
    __syncthreads();

    int mat = lane >> 3, mr = lane & 7;
    int fr_row = (mat & 1) * 8 + mr, fr_ch = mat >> 1;
    int wm = wid * 16;
    int tr = lane >> 2, tq = lane & 3;

    uint32_t qf[8][4];
#pragma unroll
    for (int kk = 0; kk < 8; kk++)
        ldsm4(qf[kk], qbase + (kk >> 1) * 8192 + swoff(wm + fr_row, (kk & 1) * 2 + fr_ch));

    float o_acc[16][4];
#pragma unroll
    for (int j = 0; j < 16; j++)
#pragma unroll
        for (int q = 0; q < 4; q++) o_acc[j][q] = 0.f;
    float m_run[2] = { -INFINITY, -INFINITY };
    float l_run[2] = { 0.f, 0.f };

    const float SC = 0.08838834764831845f * 1.4426950408889634f;
    int rowg0 = qt * 128 + wm + tr;

    for (int kt = 0; kt < nkt; kt++) {
        if (kt > 0) { CP_WAIT(1); __syncthreads(); }
        uint32_t st = smb + 32768 + (uint32_t)(kt & 1) * AT_STAGE;

        // ---- S = Q K^T over 128 cols: 16 n8 accumulators ----
        float s_acc[16][4];
#pragma unroll
        for (int j = 0; j < 16; j++)
#pragma unroll
            for (int q = 0; q < 4; q++) s_acc[j][q] = 0.f;
#pragma unroll
        for (int kk = 0; kk < 8; kk++) {
#pragma unroll
            for (int g = 0; g < 8; g++) {
                uint32_t kf[4];
                ldsm4(kf, st + (kk >> 1) * 8192 + swoff(16 * g + fr_row, (kk & 1) * 2 + fr_ch));
                mma16816(s_acc[2 * g + 0], qf[kk], kf[0], kf[2]);
                mma16816(s_acc[2 * g + 1], qf[kk], kf[1], kf[3]);
            }
        }

        // ---- mask + scale in place, then softmax ----
#pragma unroll
        for (int j = 0; j < 16; j++)
#pragma unroll
            for (int q = 0; q < 4; q++) {
                int colg = kt * 128 + j * 8 + tq * 2 + (q & 1);
                int rowg = rowg0 + (q >> 1) * 8;
                float x = s_acc[j][q] * SC;
                s_acc[j][q] = (colg <= rowg) ? x : -1e30f;
            }
        float mrow0 = -1e30f, mrow1 = -1e30f;
#pragma unroll
        for (int j = 0; j < 16; j++) {
            mrow0 = fmaxf(mrow0, fmaxf(s_acc[j][0], s_acc[j][1]));
            mrow1 = fmaxf(mrow1, fmaxf(s_acc[j][2], s_acc[j][3]));
        }
        mrow0 = fmaxf(mrow0, __shfl_xor_sync(0xFFFFFFFF, mrow0, 1));
        mrow0 = fmaxf(mrow0, __shfl_xor_sync(0xFFFFFFFF, mrow0, 2));
        mrow1 = fmaxf(mrow1, __shfl_xor_sync(0xFFFFFFFF, mrow1, 1));
        mrow1 = fmaxf(mrow1, __shfl_xor_sync(0xFFFFFFFF, mrow1, 2));
        float mnew0 = fmaxf(m_run[0], mrow0);
        float mnew1 = fmaxf(m_run[1], mrow1);
        float alpha0 = ex2(m_run[0] - mnew0);
        float alpha1 = ex2(m_run[1] - mnew1);
        float rs0 = 0.f, rs1 = 0.f;
#pragma unroll
        for (int j = 0; j < 16; j++) {
            s_acc[j][0] = ex2(s_acc[j][0] - mnew0);
            s_acc[j][1] = ex2(s_acc[j][1] - mnew0);
            s_acc[j][2] = ex2(s_acc[j][2] - mnew1);
            s_acc[j][3] = ex2(s_acc[j][3] - mnew1);
            rs0 += s_acc[j][0] + s_acc[j][1];
            rs1 += s_acc[j][2] + s_acc[j][3];
        }
        rs0 += __shfl_xor_sync(0xFFFFFFFF, rs0, 1);
        rs0 += __shfl_xor_sync(0xFFFFFFFF, rs0, 2);
        rs1 += __shfl_xor_sync(0xFFFFFFFF, rs1, 1);
        rs1 += __shfl_xor_sync(0xFFFFFFFF, rs1, 2);
        l_run[0] = l_run[0] * alpha0 + rs0;
        l_run[1] = l_run[1] * alpha1 + rs1;
        m_run[0] = mnew0;
        m_run[1] = mnew1;
#pragma unroll
        for (int jj = 0; jj < 16; jj++) {
            o_acc[jj][0] *= alpha0; o_acc[jj][1] *= alpha0;
            o_acc[jj][2] *= alpha1; o_acc[jj][3] *= alpha1;
        }

        // ---- P fragments: 4 vs-quarters x 2 k16 frags each ----
        uint32_t pa[4][2][4];
#pragma unroll
        for (int vs = 0; vs < 4; vs++)
#pragma unroll
            for (int t = 0; t < 2; t++) {
                int j0 = vs * 4 + 2 * t;
                pa[vs][t][0] = f22u(s_acc[j0][0],   s_acc[j0][1]);
                pa[vs][t][1] = f22u(s_acc[j0][2],   s_acc[j0][3]);
                pa[vs][t][2] = f22u(s_acc[j0+1][0], s_acc[j0+1][1]);
                pa[vs][t][3] = f22u(s_acc[j0+1][2], s_acc[j0+1][3]);
            }

        // ---- O += P V (4 vs-quarters of 32 k each) ----
#pragma unroll
        for (int vs = 0; vs < 4; vs++) {
#pragma unroll
            for (int g = 0; g < 8; g++) {
#pragma unroll
                for (int t = 0; t < 2; t++) {
                    uint32_t vb[4];
                    ldsm4(vb, st + 32768 + vs * 8192 + swoff(16 * g + fr_row, t * 2 + fr_ch));
                    mma16816(o_acc[2 * g + 0], pa[vs][t], vb[0], vb[2]);
                    mma16816(o_acc[2 * g + 1], pa[vs][t], vb[1], vb[3]);
                }
            }
        }

        if (kt + 2 < nkt) {
            __syncthreads();
            load_stage(kt + 2);
            CP_COMMIT();
        } else {
            CP_COMMIT();   // keep group count aligned for CP_WAIT(1)
        }
    }

    // ---- epilogue ----
    float inv0 = 1.0f / l_run[0];
    float inv1 = 1.0f / l_run[1];
    int b = bh >> 4, h = bh & 15;
    int sg0 = qt * 128 + wm + tr;
#pragma unroll
    for (int jj = 0; jj < 16; jj++) {
        int dcol = jj * 8 + tq * 2;
        size_t a0 = ((size_t)(b * Sdim + sg0)) * Hdim + h * 128 + dcol;
        size_t a1 = ((size_t)(b * Sdim + sg0 + 8)) * Hdim + h * 128 + dcol;
        *(__half2*)(g_ctxh + a0) = __floats2half2_rn(o_acc[jj][0] * inv0, o_acc[jj][1] * inv0);
        *(__half2*)(g_ctxh + a1) = __floats2half2_rn(o_acc[jj][2] * inv1, o_acc[jj][3] * inv1);
    }
}

// ============================ mask passthrough ============================
__global__ void mask_kernel(const unsigned char* __restrict__ m, float* __restrict__ o, int n) {
    int i = blockIdx.x * blockDim.x + threadIdx.x;
    if (i < n) o[i] = m[i] ? 1.0f : 0.0f;
}

// ============================ launch ============================
extern "C" void kernel_launch(void* const* d_in, const int* in_sizes, int n_in,
                              void* d_out, int out_size) {
    const float* hs            = (const float*)d_in[0];
    const unsigned char* mask  = (const unsigned char*)d_in[1];
    const float* ln1w          = (const float*)d_in[2];
    const float* ln1b          = (const float*)d_in[3];
    const float* wqkv          = (const float*)d_in[4];
    const float* bqkv          = (const float*)d_in[5];
    const float* wdense        = (const float*)d_in[6];
    const float* bdense        = (const float*)d_in[7];
    const float* ln2w          = (const float*)d_in[8];
    const float* ln2b          = (const float*)d_in[9];
    const float* w1            = (const float*)d_in[10];
    const float* b1            = (const float*)d_in[11];
    const float* w2            = (const float*)d_in[12];
    const float* b2            = (const float*)d_in[13];
    float* out = (float*)d_out;

    float *phid;
    __half *pxh, *pctxh, *pinterh, *pqkvh, *pwqkvh, *pwdh, *pw1h, *pw2h;
    cudaGetSymbolAddress((void**)&phid,   g_hidden);
    cudaGetSymbolAddress((void**)&pxh,    g_xh);
    cudaGetSymbolAddress((void**)&pctxh,  g_ctxh);
    cudaGetSymbolAddress((void**)&pinterh, g_interh);
    cudaGetSymbolAddress((void**)&pqkvh,  g_qkvh);
    cudaGetSymbolAddress((void**)&pwqkvh, g_wqkvh);
    cudaGetSymbolAddress((void**)&pwdh,   g_wdh);
    cudaGetSymbolAddress((void**)&pw1h,   g_w1h);
    cudaGetSymbolAddress((void**)&pw2h,   g_w2h);

    cudaFuncSetAttribute(attn_kernel, cudaFuncAttributeMaxDynamicSharedMemorySize, AT_SMEM);
    cudaFuncSetAttribute(hgemm<1>, cudaFuncAttributeMaxDynamicSharedMemorySize, HM_SMEM);
    cudaFuncSetAttribute(hgemm<2>, cudaFuncAttributeMaxDynamicSharedMemorySize, HM_SMEM);
    cudaFuncSetAttribute(hgemm<3>, cudaFuncAttributeMaxDynamicSharedMemorySize, HM_SMEM);

    // weight prep: fp32 -> fp16 (vectorized)
    cvt_kernel<<<(3*Hdim*Hdim/8 + 255)/256, 256>>>(wqkv, pwqkvh, 3*Hdim*Hdim/8);
    cvt_kernel<<<(Hdim*Hdim/8   + 255)/256, 256>>>(wdense, pwdh, Hdim*Hdim/8);
    cvt_kernel<<<(FFdim*Hdim/8  + 255)/256, 256>>>(w1,     pw1h, FFdim*Hdim/8);
    cvt_kernel<<<(Hdim*FFdim/8  + 255)/256, 256>>>(w2,     pw2h, Hdim*FFdim/8);
    // LN1 -> xh
    ln_kernel<<<Mrows, 256>>>(hs, ln1w, ln1b, pxh);
    // RoPE trig table
    rope_table_kernel<<<(Sdim * 64) / 256, 256>>>();
    // QKV = x @ wqkv^T + bqkv (half out, fp32 acc)
    hgemm<3><<<dim3(3 * Hdim / GBN, Mrows / GBM), 512, HM_SMEM>>>(
        pxh, pwqkvh, bqkv, nullptr, nullptr, pqkvh, Mrows, 3 * Hdim, Hdim);
    // split + rope -> qh/kh (half, [B,NH,S,D])
    rope_kernel<<<dim3(Mrows, NHdim), 128>>>();
    // V transpose (direct from qkvh) -> vt (half, [B,NH,D,S])
    vt_kernel<<<dim3(Sdim / 64, Ddim / 64, Bdim * NHdim), 256>>>();
    // HMMA flash attention (Bc=128) -> ctxh
    attn_kernel<<<dim3(Sdim / 128, Bdim * NHdim), 256, AT_SMEM>>>();
    // dense + residual(hidden_states) -> g_hidden (fp32)
    hgemm<2><<<dim3(Hdim / GBN, Mrows / GBM), 512, HM_SMEM>>>(
        pctxh, pwdh, bdense, hs, phid, nullptr, Mrows, Hdim, Hdim);
    // LN2 -> xh
    ln_kernel<<<Mrows, 256>>>(phid, ln2w, ln2b, pxh);
    // FF1 + GELU -> interh (fp16)
    hgemm<1><<<dim3(FFdim / GBN, Mrows / GBM), 512, HM_SMEM>>>(
        pxh, pw1h, b1, nullptr, nullptr, pinterh, Mrows, FFdim, Hdim);
    // FF2 + residual(g_hidden) -> out
    hgemm<2><<<dim3(Hdim / GBN, Mrows / GBM), 512, HM_SMEM>>>(
        pinterh, pw2h, b2, phid, out, nullptr, Mrows, Hdim, FFdim);
    // if output also carries the attention mask, convert it after hidden
    long long hid_elems = (long long)Mrows * Hdim;           // 8388608
    long long mask_elems = (long long)Sdim * Sdim;           // 4194304
    if ((long long)out_size >= hid_elems + mask_elems) {
        mask_kernel<<<(int)(mask_elems / 256), 256>>>(mask, out + hid_elems, (int)mask_elems);
    }
}